// round 13
// baseline (speedup 1.0000x reference)
#include <cuda_runtime.h>
#include <math.h>
#include <stdint.h>

// Problem constants
#define B_   16
#define C_   512
#define NH_  8
#define HD_  64
#define N_   1024
#define QSCALE 0.125f

typedef unsigned long long ull;

// ---------------------------------------------------------------------------
// Scratch (device globals) — pure fp32 pipeline.
// ---------------------------------------------------------------------------
__device__ float g_qkv[(size_t)3 * B_ * C_ * N_];   // [s][b][c][n] (Q pre-scaled)
__device__ float g_attn[(size_t)B_ * C_ * N_];      // [b][c][n]

// ---------------------------------------------------------------------------
// Packed f32x2 helpers (sm_100+ family PTX)
// ---------------------------------------------------------------------------
__device__ __forceinline__ ull pk2(float x, float y) {
    ull r;
    asm("mov.b64 %0, {%1, %2};"
        : "=l"(r) : "r"(__float_as_uint(x)), "r"(__float_as_uint(y)));
    return r;
}
__device__ __forceinline__ void up2(ull v, float& x, float& y) {
    uint32_t a, b;
    asm("mov.b64 {%0, %1}, %2;" : "=r"(a), "=r"(b) : "l"(v));
    x = __uint_as_float(a); y = __uint_as_float(b);
}
__device__ __forceinline__ ull fma2(ull a, ull b, ull c) {
    ull d;
    asm("fma.rn.f32x2 %0, %1, %2, %3;" : "=l"(d) : "l"(a), "l"(b), "l"(c));
    return d;
}
__device__ __forceinline__ ull mul2(ull a, ull b) {
    ull d;
    asm("mul.rn.f32x2 %0, %1, %2;" : "=l"(d) : "l"(a), "l"(b));
    return d;
}

// ---------------------------------------------------------------------------
// f32x2 GEMM (R9 exact — known 743 us / ~250 us):
// D[o][n] = sum_c W[o][c] * X[b][c][n].
// Block 128(o) x 128(n), BK=16, 256 threads (16x16), 8x8 micro-tile.
// MODE 0: scatter fp32 into g_qkv (Q rows scaled).  MODE 1: +bias -> out.
// ---------------------------------------------------------------------------
template<int MODE>
__global__ __launch_bounds__(256)
void gemm_f32x2(const float* __restrict__ W, const float* __restrict__ Xin,
                const float* __restrict__ bias, float* __restrict__ out)
{
    __shared__ ull   As2[16][128];   // [k][o], each entry = (a, a)   (16 KB)
    __shared__ float Bs[16][128];    // [k][n]                         (8 KB)

    const int b  = blockIdx.z;
    const int o0 = blockIdx.x * 128;
    const int n0 = blockIdx.y * 128;
    const int tid = threadIdx.x;
    const int tx = tid & 15, ty = tid >> 4;

    const float* Xb = (MODE == 1 ? g_attn : Xin) + (size_t)b * C_ * N_;

    ull acc[8][4];
    #pragma unroll
    for (int i = 0; i < 8; i++)
        #pragma unroll
        for (int j = 0; j < 4; j++) acc[i][j] = 0ull;

    for (int kt = 0; kt < C_; kt += 16) {
        // A: 128 o x 16 k, duplicated into ull pairs
        #pragma unroll
        for (int r = 0; r < 2; r++) {
            int idx = tid + r * 256;           // 0..511 float4 units
            int m = idx >> 2, q = idx & 3;
            float4 a4 = *(const float4*)&W[(size_t)(o0 + m) * C_ + kt + q * 4];
            As2[q * 4 + 0][m] = pk2(a4.x, a4.x);
            As2[q * 4 + 1][m] = pk2(a4.y, a4.y);
            As2[q * 4 + 2][m] = pk2(a4.z, a4.z);
            As2[q * 4 + 3][m] = pk2(a4.w, a4.w);
        }
        // B: 16 k x 128 n
        #pragma unroll
        for (int r = 0; r < 2; r++) {
            int idx = tid + r * 256;           // 0..511 float4 units
            int k = idx >> 5, j4 = idx & 31;
            *(float4*)&Bs[k][j4 * 4] =
                *(const float4*)&Xb[(size_t)(kt + k) * N_ + n0 + j4 * 4];
        }
        __syncthreads();

        #pragma unroll
        for (int k = 0; k < 16; k++) {
            ull aa[8];
            #pragma unroll
            for (int i = 0; i < 8; i++) aa[i] = As2[k][ty * 8 + i];
            ulonglong2 b20 = *(const ulonglong2*)&Bs[k][tx * 8];
            ulonglong2 b21 = *(const ulonglong2*)&Bs[k][tx * 8 + 4];
            ull b2[4] = { b20.x, b20.y, b21.x, b21.y };
            #pragma unroll
            for (int i = 0; i < 8; i++)
                #pragma unroll
                for (int j = 0; j < 4; j++)
                    acc[i][j] = fma2(aa[i], b2[j], acc[i][j]);
        }
        __syncthreads();
    }

    #pragma unroll
    for (int i = 0; i < 8; i++) {
        int o = o0 + ty * 8 + i;
        float scale = 1.f, bv = 0.f;
        float* dst;
        if (MODE == 0) {
            int s = o >> 9, rem = o & 511;
            if (s == 0) scale = QSCALE;
            dst = g_qkv + (((size_t)s * B_ + b) * C_ + rem) * N_ + n0;
        } else {
            bv = bias[o];
            dst = out + ((size_t)b * C_ + o) * N_ + n0;
        }
        #pragma unroll
        for (int j = 0; j < 4; j++) {
            float x, y;
            up2(acc[i][j], x, y);
            float2 v;
            if (MODE == 0) { v.x = x * scale; v.y = y * scale; }
            else           { v.x = x + bv;    v.y = y + bv; }
            *(float2*)(dst + tx * 8 + j * 2) = v;
        }
    }
}

// ---------------------------------------------------------------------------
// f32x2 flash attention v3: LANE-PAIRED. Adjacent lanes (tid, tid^1) share
// one query; each owns 32 of the 64 head dims. q2/o2 register arrays halve
// (regs ~110 -> 4 blocks/SM), per-key LDS+fma2 halve; score combined with
// one shfl.xor(1). Softmax state duplicated per pair (deterministic).
// Block = 128 threads = 64 queries. Grid (BH, N/64).
// ---------------------------------------------------------------------------
__global__ __launch_bounds__(128)
void attn_f32x2()
{
    __shared__ float Ks[64][68];   // [j][d], 272B rows (16B-aligned)
    __shared__ float Vs[64][68];

    const int bh = blockIdx.x;
    const int b  = bh >> 3, h = bh & 7;
    const int tid = threadIdx.x;
    const int half = tid & 1;                  // 0: dims 0-31, 1: dims 32-63
    const int n  = blockIdx.y * 64 + (tid >> 1);
    const int dbase = half * 32;

    const size_t headoff = ((size_t)b * C_ + h * HD_) * N_;
    const float* Qg = g_qkv + headoff;                               // pre-scaled
    const float* Kg = g_qkv + (size_t)1 * B_ * C_ * N_ + headoff;
    const float* Vg = g_qkv + (size_t)2 * B_ * C_ * N_ + headoff;

    ull q2[16], o2[16];
    #pragma unroll
    for (int dp = 0; dp < 16; dp++) {
        q2[dp] = pk2(Qg[(size_t)(dbase + 2 * dp) * N_ + n],
                     Qg[(size_t)(dbase + 2 * dp + 1) * N_ + n]);
        o2[dp] = 0ull;
    }
    float m = -INFINITY, l = 0.f;

    for (int t0 = 0; t0 < N_; t0 += 64) {
        // transposed tile loads: gmem [d][n] -> smem [j][d]
        #pragma unroll
        for (int it = 0; it < 8; it++) {
            int f = it * 128 + tid;        // 0..1023
            int d = f >> 4, j4 = f & 15;
            float4 kk = *(const float4*)&Kg[(size_t)d * N_ + t0 + j4 * 4];
            Ks[j4 * 4 + 0][d] = kk.x; Ks[j4 * 4 + 1][d] = kk.y;
            Ks[j4 * 4 + 2][d] = kk.z; Ks[j4 * 4 + 3][d] = kk.w;
            float4 vv = *(const float4*)&Vg[(size_t)d * N_ + t0 + j4 * 4];
            Vs[j4 * 4 + 0][d] = vv.x; Vs[j4 * 4 + 1][d] = vv.y;
            Vs[j4 * 4 + 2][d] = vv.z; Vs[j4 * 4 + 3][d] = vv.w;
        }
        __syncthreads();

        for (int j4 = 0; j4 < 16; j4++) {
            // scores for 4 keys: each lane does its 32-dim half, then pair-sum
            float s[4];
            #pragma unroll
            for (int jj = 0; jj < 4; jj++) {
                const ulonglong2* kp = (const ulonglong2*)&Ks[j4 * 4 + jj][dbase];
                ull sa = 0ull, sb = 0ull;
                #pragma unroll
                for (int dq = 0; dq < 8; dq++) {
                    ulonglong2 k2 = kp[dq];
                    sa = fma2(q2[2 * dq],     k2.x, sa);
                    sb = fma2(q2[2 * dq + 1], k2.y, sb);
                }
                float ax, ay, bx, by;
                up2(sa, ax, ay); up2(sb, bx, by);
                float sh = (ax + bx) + (ay + by);
                s[jj] = sh + __shfl_xor_sync(0xffffffffu, sh, 1);
            }

            // online softmax (identical in both lanes of a pair)
            float gm = fmaxf(fmaxf(s[0], s[1]), fmaxf(s[2], s[3]));
            if (gm > m) {
                float corr = __expf(m - gm);        // exp(-inf)=0 first tile
                l *= corr;
                ull cc = pk2(corr, corr);
                #pragma unroll
                for (int dp = 0; dp < 16; dp++) o2[dp] = mul2(o2[dp], cc);
                m = gm;
            }
            float p[4];
            #pragma unroll
            for (int jj = 0; jj < 4; jj++) { p[jj] = __expf(s[jj] - m); l += p[jj]; }

            // PV accumulate (own 32-dim half)
            #pragma unroll
            for (int jj = 0; jj < 4; jj++) {
                ull pp = pk2(p[jj], p[jj]);
                const ulonglong2* vp = (const ulonglong2*)&Vs[j4 * 4 + jj][dbase];
                #pragma unroll
                for (int dq = 0; dq < 8; dq++) {
                    ulonglong2 v2 = vp[dq];
                    o2[2 * dq]     = fma2(pp, v2.x, o2[2 * dq]);
                    o2[2 * dq + 1] = fma2(pp, v2.y, o2[2 * dq + 1]);
                }
            }
        }
        __syncthreads();
    }

    const float inv = 1.f / l;
    float* Og = g_attn + headoff;
    #pragma unroll
    for (int dp = 0; dp < 16; dp++) {
        float x, y;
        up2(o2[dp], x, y);
        Og[(size_t)(dbase + 2 * dp) * N_ + n]     = x * inv;
        Og[(size_t)(dbase + 2 * dp + 1) * N_ + n] = y * inv;
    }
}

// ---------------------------------------------------------------------------
extern "C" void kernel_launch(void* const* d_in, const int* in_sizes, int n_in,
                              void* d_out, int out_size)
{
    const float* x      = (const float*)d_in[0];   // [B, C, H, W]
    const float* w_qkv  = (const float*)d_in[1];   // [3C, C]
    const float* w_proj = (const float*)d_in[2];   // [C, C]
    const float* b_proj = (const float*)d_in[3];   // [C]
    float* out = (float*)d_out;

    // 1) QKV GEMM (f32x2, R9-exact) -> g_qkv, Q scaled
    gemm_f32x2<0><<<dim3(3 * C_ / 128, N_ / 128, B_), 256>>>(w_qkv, x, nullptr, nullptr);

    // 2) lane-paired flash attention (f32x2) -> g_attn
    attn_f32x2<<<dim3(B_ * NH_, N_ / 64), 128>>>();

    // 3) proj GEMM (f32x2, R9-exact) + bias -> out
    gemm_f32x2<1><<<dim3(C_ / 128, N_ / 128, B_), 256>>>(w_proj, nullptr, b_proj, out);
}

// round 14
// speedup vs baseline: 1.3934x; 1.3934x over previous
#include <cuda_runtime.h>
#include <math.h>
#include <stdint.h>

// Problem constants
#define B_   16
#define C_   512
#define NH_  8
#define HD_  64
#define N_   1024
#define QSCALE 0.125f

typedef unsigned long long ull;

// ---------------------------------------------------------------------------
// Scratch (device globals) — pure fp32 pipeline.
// ---------------------------------------------------------------------------
__device__ float g_qkv[(size_t)3 * B_ * C_ * N_];   // [s][b][c][n] (Q pre-scaled)
__device__ float g_attn[(size_t)B_ * C_ * N_];      // [b][c][n]

// ---------------------------------------------------------------------------
// Packed f32x2 helpers (sm_100+ family PTX)
// ---------------------------------------------------------------------------
__device__ __forceinline__ ull pk2(float x, float y) {
    ull r;
    asm("mov.b64 %0, {%1, %2};"
        : "=l"(r) : "r"(__float_as_uint(x)), "r"(__float_as_uint(y)));
    return r;
}
__device__ __forceinline__ void up2(ull v, float& x, float& y) {
    uint32_t a, b;
    asm("mov.b64 {%0, %1}, %2;" : "=r"(a), "=r"(b) : "l"(v));
    x = __uint_as_float(a); y = __uint_as_float(b);
}
__device__ __forceinline__ ull fma2(ull a, ull b, ull c) {
    ull d;
    asm("fma.rn.f32x2 %0, %1, %2, %3;" : "=l"(d) : "l"(a), "l"(b), "l"(c));
    return d;
}
__device__ __forceinline__ ull mul2(ull a, ull b) {
    ull d;
    asm("mul.rn.f32x2 %0, %1, %2;" : "=l"(d) : "l"(a), "l"(b));
    return d;
}

// ---------------------------------------------------------------------------
// f32x2 GEMM v3: same micro-kernel as R9, BK 16 -> 32 (half the barriers).
// D[o][n] = sum_c W[o][c] * X[b][c][n].
// Block 128(o) x 128(n), BK=32, 256 threads (16x16), 8x8 micro-tile.
// smem 48KB/block -> still 2 blocks/SM. Inner loop & regs unchanged (<=128).
// MODE 0: scatter fp32 into g_qkv (Q rows scaled).  MODE 1: +bias -> out.
// ---------------------------------------------------------------------------
template<int MODE>
__global__ __launch_bounds__(256)
void gemm_f32x2(const float* __restrict__ W, const float* __restrict__ Xin,
                const float* __restrict__ bias, float* __restrict__ out)
{
    __shared__ ull   As2[32][128];   // [k][o], each entry = (a, a)   (32 KB)
    __shared__ float Bs[32][128];    // [k][n]                         (16 KB)

    const int b  = blockIdx.z;
    const int o0 = blockIdx.x * 128;
    const int n0 = blockIdx.y * 128;
    const int tid = threadIdx.x;
    const int tx = tid & 15, ty = tid >> 4;

    const float* Xb = (MODE == 1 ? g_attn : Xin) + (size_t)b * C_ * N_;

    ull acc[8][4];
    #pragma unroll
    for (int i = 0; i < 8; i++)
        #pragma unroll
        for (int j = 0; j < 4; j++) acc[i][j] = 0ull;

    for (int kt = 0; kt < C_; kt += 32) {
        // A: 128 o x 32 k, duplicated into ull pairs (1024 float4 / 256 thr)
        #pragma unroll
        for (int r = 0; r < 4; r++) {
            int idx = tid + r * 256;           // 0..1023 float4 units
            int m = idx >> 3, q = idx & 7;
            float4 a4 = *(const float4*)&W[(size_t)(o0 + m) * C_ + kt + q * 4];
            As2[q * 4 + 0][m] = pk2(a4.x, a4.x);
            As2[q * 4 + 1][m] = pk2(a4.y, a4.y);
            As2[q * 4 + 2][m] = pk2(a4.z, a4.z);
            As2[q * 4 + 3][m] = pk2(a4.w, a4.w);
        }
        // B: 32 k x 128 n (1024 float4 / 256 thr)
        #pragma unroll
        for (int r = 0; r < 4; r++) {
            int idx = tid + r * 256;           // 0..1023 float4 units
            int k = idx >> 5, j4 = idx & 31;
            *(float4*)&Bs[k][j4 * 4] =
                *(const float4*)&Xb[(size_t)(kt + k) * N_ + n0 + j4 * 4];
        }
        __syncthreads();

        #pragma unroll
        for (int k = 0; k < 32; k++) {
            ull aa[8];
            #pragma unroll
            for (int i = 0; i < 8; i++) aa[i] = As2[k][ty * 8 + i];
            ulonglong2 b20 = *(const ulonglong2*)&Bs[k][tx * 8];
            ulonglong2 b21 = *(const ulonglong2*)&Bs[k][tx * 8 + 4];
            ull b2[4] = { b20.x, b20.y, b21.x, b21.y };
            #pragma unroll
            for (int i = 0; i < 8; i++)
                #pragma unroll
                for (int j = 0; j < 4; j++)
                    acc[i][j] = fma2(aa[i], b2[j], acc[i][j]);
        }
        __syncthreads();
    }

    #pragma unroll
    for (int i = 0; i < 8; i++) {
        int o = o0 + ty * 8 + i;
        float scale = 1.f, bv = 0.f;
        float* dst;
        if (MODE == 0) {
            int s = o >> 9, rem = o & 511;
            if (s == 0) scale = QSCALE;
            dst = g_qkv + (((size_t)s * B_ + b) * C_ + rem) * N_ + n0;
        } else {
            bv = bias[o];
            dst = out + ((size_t)b * C_ + o) * N_ + n0;
        }
        #pragma unroll
        for (int j = 0; j < 4; j++) {
            float x, y;
            up2(acc[i][j], x, y);
            float2 v;
            if (MODE == 0) { v.x = x * scale; v.y = y * scale; }
            else           { v.x = x + bv;    v.y = y + bv; }
            *(float2*)(dst + tx * 8 + j * 2) = v;
        }
    }
}

// ---------------------------------------------------------------------------
// f32x2 flash attention (R9-EXACT — known ~1160 us): 1 thread = 1 query.
// K,V tiles transposed to [j][d] in smem; q/o packed as f32x2 d-pairs.
// ---------------------------------------------------------------------------
__global__ __launch_bounds__(128)
void attn_f32x2()
{
    __shared__ float Ks[64][68];
    __shared__ float Vs[64][68];

    const int bh = blockIdx.x;
    const int b  = bh >> 3, h = bh & 7;
    const int tid = threadIdx.x;
    const int n  = blockIdx.y * 128 + tid;

    const size_t headoff = ((size_t)b * C_ + h * HD_) * N_;
    const float* Qg = g_qkv + headoff;                               // pre-scaled
    const float* Kg = g_qkv + (size_t)1 * B_ * C_ * N_ + headoff;
    const float* Vg = g_qkv + (size_t)2 * B_ * C_ * N_ + headoff;

    ull q2[32], o2[32];
    #pragma unroll
    for (int dp = 0; dp < 32; dp++) {
        q2[dp] = pk2(Qg[(size_t)(2 * dp) * N_ + n], Qg[(size_t)(2 * dp + 1) * N_ + n]);
        o2[dp] = 0ull;
    }
    float m = -INFINITY, l = 0.f;

    for (int t0 = 0; t0 < N_; t0 += 64) {
        // transposed tile loads: gmem [d][n] -> smem [j][d]
        #pragma unroll
        for (int it = 0; it < 8; it++) {
            int f = it * 128 + tid;        // 0..1023
            int d = f >> 4, j4 = f & 15;
            float4 kk = *(const float4*)&Kg[(size_t)d * N_ + t0 + j4 * 4];
            Ks[j4 * 4 + 0][d] = kk.x; Ks[j4 * 4 + 1][d] = kk.y;
            Ks[j4 * 4 + 2][d] = kk.z; Ks[j4 * 4 + 3][d] = kk.w;
            float4 vv = *(const float4*)&Vg[(size_t)d * N_ + t0 + j4 * 4];
            Vs[j4 * 4 + 0][d] = vv.x; Vs[j4 * 4 + 1][d] = vv.y;
            Vs[j4 * 4 + 2][d] = vv.z; Vs[j4 * 4 + 3][d] = vv.w;
        }
        __syncthreads();

        for (int j4 = 0; j4 < 16; j4++) {
            // scores for 4 keys
            float s[4];
            #pragma unroll
            for (int jj = 0; jj < 4; jj++) {
                const ulonglong2* kp = (const ulonglong2*)&Ks[j4 * 4 + jj][0];
                ull sa = 0ull, sb = 0ull;           // 2 chains for ILP
                #pragma unroll
                for (int dq = 0; dq < 16; dq++) {
                    ulonglong2 k2 = kp[dq];         // broadcast LDS.128
                    sa = fma2(q2[2 * dq],     k2.x, sa);
                    sb = fma2(q2[2 * dq + 1], k2.y, sb);
                }
                float ax, ay, bx, by;
                up2(sa, ax, ay); up2(sb, bx, by);
                s[jj] = (ax + bx) + (ay + by);
            }

            // online softmax (lazy rescale)
            float gm = fmaxf(fmaxf(s[0], s[1]), fmaxf(s[2], s[3]));
            if (gm > m) {
                float corr = __expf(m - gm);        // exp(-inf)=0 first tile
                l *= corr;
                ull cc = pk2(corr, corr);
                #pragma unroll
                for (int dp = 0; dp < 32; dp++) o2[dp] = mul2(o2[dp], cc);
                m = gm;
            }
            float p[4];
            #pragma unroll
            for (int jj = 0; jj < 4; jj++) { p[jj] = __expf(s[jj] - m); l += p[jj]; }

            // PV accumulate
            #pragma unroll
            for (int jj = 0; jj < 4; jj++) {
                ull pp = pk2(p[jj], p[jj]);
                const ulonglong2* vp = (const ulonglong2*)&Vs[j4 * 4 + jj][0];
                #pragma unroll
                for (int dq = 0; dq < 16; dq++) {
                    ulonglong2 v2 = vp[dq];         // broadcast LDS.128
                    o2[2 * dq]     = fma2(pp, v2.x, o2[2 * dq]);
                    o2[2 * dq + 1] = fma2(pp, v2.y, o2[2 * dq + 1]);
                }
            }
        }
        __syncthreads();
    }

    const float inv = 1.f / l;
    float* Og = g_attn + headoff;
    #pragma unroll
    for (int dp = 0; dp < 32; dp++) {
        float x, y;
        up2(o2[dp], x, y);
        Og[(size_t)(2 * dp) * N_ + n]     = x * inv;   // coalesced per d
        Og[(size_t)(2 * dp + 1) * N_ + n] = y * inv;
    }
}

// ---------------------------------------------------------------------------
extern "C" void kernel_launch(void* const* d_in, const int* in_sizes, int n_in,
                              void* d_out, int out_size)
{
    const float* x      = (const float*)d_in[0];   // [B, C, H, W]
    const float* w_qkv  = (const float*)d_in[1];   // [3C, C]
    const float* w_proj = (const float*)d_in[2];   // [C, C]
    const float* b_proj = (const float*)d_in[3];   // [C]
    float* out = (float*)d_out;

    // 1) QKV GEMM (f32x2, BK=32) -> g_qkv, Q scaled
    gemm_f32x2<0><<<dim3(3 * C_ / 128, N_ / 128, B_), 256>>>(w_qkv, x, nullptr, nullptr);

    // 2) flash attention (f32x2, R9-exact) -> g_attn
    attn_f32x2<<<dim3(B_ * NH_, N_ / 128), 128>>>();

    // 3) proj GEMM (f32x2, BK=32) + bias -> out
    gemm_f32x2<1><<<dim3(C_ / 128, N_ / 128, B_), 256>>>(w_proj, nullptr, b_proj, out);
}